// round 8
// baseline (speedup 1.0000x reference)
#include <cuda_runtime.h>

// ============================================================================
// Connect_Loss: opening(cross) -> global minmax norm -> binarize(0.5)
//   -> 150 iters of fg-masked 3x3 maxpool label propagation (exact)
//   -> count distinct labels -> |ccsg - ccs| / numSg  (scalar out)
// Shapes: img, lab: (4,1,1024,1024) fp32. 8 slices of 1024^2 total.
//
// Persistent propagation: one kernel, software global barrier between rounds,
// bit-exact early exit at the global fixed point (identity step => identity
// forever). Distinct count via fin[p]==p+1 (component-max property), no map.
// ============================================================================

#define NPIX  (8u << 20)            // 8,388,608 px total (2 tensors)

__device__ int   g_labA[NPIX];               // label ping
__device__ int   g_labB[NPIX];               // label pong (also float scratch: opened img)
__device__ unsigned int  g_red[4];           // mn0,mx0,mn1,mx1 as uint bits (nonneg floats)
__device__ unsigned int  g_cnt[4];           // distinct0, distinct1, numSg, unused
__device__ unsigned int  g_zf[2];            // background-exists flags
__device__ unsigned int  g_chgs[32];         // per-round "anything changed" flags
__device__ unsigned int  g_last;             // last round that actually ran
__device__ unsigned int  g_bar_cnt;          // barrier arrival counter
__device__ unsigned int  g_bar_gen;          // barrier generation

// ---------------------------------------------------------------------------
__global__ void k_init() {
  int tid = threadIdx.x;
  if (tid < 32) g_chgs[tid] = 0u;
  if (tid == 0) {
    g_red[0] = 0x7f800000u; g_red[1] = 0u;   // +inf / 0 (values are nonneg)
    g_red[2] = 0x7f800000u; g_red[3] = 0u;
    g_cnt[0] = 0u; g_cnt[1] = 0u; g_cnt[2] = 0u; g_cnt[3] = 0u;
    g_zf[0] = 0u; g_zf[1] = 0u;
    g_bar_cnt = 0u; g_last = 0u;
  }
}

// ---------------------------------------------------------------------------
// fused opening: erosion (min cross, +BIG pad) then dilation (max cross,
// -BIG pad), all in shared memory; stores opened value (float, into g_labB)
// and reduces per-tensor global min/max.
// Block: 256 thr; interior 64x16; RAW tile 68x20 (halo 2), ER 66x18 (halo 1).
// ---------------------------------------------------------------------------
#define OX 64
#define OY 16

__global__ void __launch_bounds__(256) k_open(const float* __restrict__ img,
                                              const float* __restrict__ lab) {
  __shared__ float RAW[OY + 4][OX + 4];   // 20 x 68
  __shared__ float ER[OY + 2][OX + 4];    // 18 x 68 (66 used)
  __shared__ float smn[8], smx[8];

  unsigned s = blockIdx.z;
  const float* __restrict__ p = (s < 4u) ? (img + (s << 20)) : (lab + ((s - 4u) << 20));
  float* __restrict__ op = ((float*)g_labB) + (s << 20);

  int gx0 = (int)blockIdx.x * OX - 2;
  int gy0 = (int)blockIdx.y * OY - 2;
  int tid = threadIdx.x;

  // load raw tile; OOB -> +BIG (erosion-neutral)
  for (int i = tid; i < (OY + 4) * (OX + 4); i += 256) {
    int ly = i / (OX + 4), lx = i - ly * (OX + 4);
    int gy = gy0 + ly, gx = gx0 + lx;
    float v = 1e30f;
    if ((unsigned)gy < 1024u && (unsigned)gx < 1024u)
      v = p[((unsigned)gy << 10) + (unsigned)gx];
    RAW[ly][lx] = v;
  }
  __syncthreads();

  // erosion ring (halo 1); OOB-position -> -BIG (dilation-neutral)
  for (int i = tid; i < (OY + 2) * (OX + 2); i += 256) {
    int ey = i / (OX + 2), ex = i - ey * (OX + 2);
    int gy = gy0 + 1 + ey, gx = gx0 + 1 + ex;
    float v = -1e30f;
    if ((unsigned)gy < 1024u && (unsigned)gx < 1024u) {
      v = RAW[ey + 1][ex + 1];
      v = fminf(v, RAW[ey][ex + 1]);
      v = fminf(v, RAW[ey + 2][ex + 1]);
      v = fminf(v, RAW[ey + 1][ex]);
      v = fminf(v, RAW[ey + 1][ex + 2]);
    }
    ER[ey][ex] = v;
  }
  __syncthreads();

  // dilation on interior (always in-bounds) + minmax reduce
  int ox = tid & 63;
  int oyb = tid >> 6;
  float mn = 3.4e38f, mx = -3.4e38f;
#pragma unroll
  for (int k = 0; k < 4; k++) {
    int oy = oyb + 4 * k;
    float v = ER[oy + 1][ox + 1];
    v = fmaxf(v, ER[oy][ox + 1]);
    v = fmaxf(v, ER[oy + 2][ox + 1]);
    v = fmaxf(v, ER[oy + 1][ox]);
    v = fmaxf(v, ER[oy + 1][ox + 2]);
    int gy = gy0 + 2 + oy, gx = gx0 + 2 + ox;
    op[((unsigned)gy << 10) + (unsigned)gx] = v;
    mn = fminf(mn, v);
    mx = fmaxf(mx, v);
  }
#pragma unroll
  for (int o = 16; o; o >>= 1) {
    mn = fminf(mn, __shfl_down_sync(0xffffffffu, mn, o));
    mx = fmaxf(mx, __shfl_down_sync(0xffffffffu, mx, o));
  }
  int w = tid >> 5;
  if ((tid & 31) == 0) { smn[w] = mn; smx[w] = mx; }
  __syncthreads();
  if (tid == 0) {
    for (int i = 1; i < 8; i++) { mn = fminf(mn, smn[i]); mx = fmaxf(mx, smx[i]); }
    unsigned t = s >> 2;
    atomicMin(&g_red[t * 2u],     __float_as_uint(mn));
    atomicMax(&g_red[t * 2u + 1], __float_as_uint(mx));
  }
}

// ---------------------------------------------------------------------------
// threshold: fg = ((op - mn) / ((mx - mn) + 1e-10)) >= 0.5  (IEEE fp32 div)
// write initial labels (tensor-local idx + 1 for fg, 0 for bg); count numSg
// ---------------------------------------------------------------------------
__global__ void k_threshold() {
  __shared__ int sc[8];
  const float* __restrict__ op = (const float*)g_labB;
  unsigned base = blockIdx.x * 4096u;
  unsigned t = base >> 22;
  float mn = __uint_as_float(g_red[t * 2u]);
  float mx = __uint_as_float(g_red[t * 2u + 1]);
  float d  = __fadd_rn(__fsub_rn(mx, mn), 1e-10f);
  int cnt = 0;
#pragma unroll
  for (int j = 0; j < 16; j++) {
    unsigned idx = base + threadIdx.x + (unsigned)j * 256u;
    float v = op[idx];
    bool fg = (__fdiv_rn(__fsub_rn(v, mn), d) >= 0.5f);
    unsigned wt = idx & 0x3FFFFFu;          // tensor-local index
    g_labA[idx] = fg ? (int)(wt + 1u) : 0;
    cnt += (fg ? 1 : 0);
  }
  if (t == 1u) {
#pragma unroll
    for (int o = 16; o; o >>= 1) cnt += __shfl_down_sync(0xffffffffu, cnt, o);
    int w = threadIdx.x >> 5;
    if ((threadIdx.x & 31) == 0) sc[w] = cnt;
    __syncthreads();
    if (threadIdx.x == 0) {
      for (int i = 1; i < 8; i++) cnt += sc[i];
      atomicAdd(&g_cnt[2], (unsigned)cnt);
    }
  }
}

// ---------------------------------------------------------------------------
// persistent propagation. Tile 64x144, 8 warps x (2 cols x 18 rows) in regs.
// One launch; software global barrier per round; exact early exit.
// All label traffic via __ldcg/__stcg (L2-coherent; no per-launch L1 flush
// inside a persistent kernel).
// ---------------------------------------------------------------------------
#define TW 64
#define TH 144
#define KROWS 18
#define RS 6
#define IW (TW - 2 * RS)   // 52
#define IH (TH - 2 * RS)   // 132
#define NTILE 1280         // 20 x 8 x 8
#define NBLK 592           // 148 SMs x 4 blocks (co-resident)

__device__ __forceinline__ void gsync() {
  __syncthreads();
  if (threadIdx.x == 0) {
    __threadfence();
    volatile unsigned* vg = &g_bar_gen;
    unsigned gen = *vg;
    if (atomicAdd(&g_bar_cnt, 1u) == NBLK - 1u) {
      atomicExch(&g_bar_cnt, 0u);
      __threadfence();
      *vg = gen + 1u;
    } else {
      while (*vg == gen) { }
      __threadfence();
    }
  }
  __syncthreads();
}

__global__ void __launch_bounds__(256, 4) k_prop_all() {
  __shared__ int2 Bex[2][2][8][32];  // [parity][top/bot][warpRow][lane]
  int lane = threadIdx.x & 31;
  int w    = threadIdx.x >> 5;
  int k0   = w * KROWS;

  int rnd;
  for (rnd = 0; rnd < 25; rnd++) {       // 25 * RS(6) = 150 exact steps max
    int flip = rnd & 1;
    const int* __restrict__ src = flip ? g_labB : g_labA;
    int* __restrict__ dst = flip ? g_labA : g_labB;
    unsigned chg = 0u;

    for (unsigned t = blockIdx.x; t < NTILE; t += NBLK) {
      unsigned s  = t / 160u;
      unsigned rr = t - s * 160u;
      unsigned ty = rr / 20u;
      unsigned tx = rr - ty * 20u;
      unsigned base = s << 20;
      int gx0 = (int)tx * IW - RS;
      int gy0 = (int)ty * IH - RS;
      int gx  = gx0 + 2 * lane;           // even; pairs never straddle 1024
      bool xin = (gx >= 0) && (gx <= 1022);
      bool xst = xin && (lane >= 3) && (lane <= 28);

      int c0[KROWS], c1[KROWS];
#pragma unroll
      for (int j = 0; j < KROWS; j++) {
        int gy = gy0 + k0 + j;
        int2 v = make_int2(0, 0);         // OOB -> 0 == background
        if (xin && (unsigned)gy < 1024u)
          v = __ldcg((const int2*)(src + base + ((unsigned)gy << 10) + (unsigned)gx));
        c0[j] = v.x; c1[j] = v.y;
      }

      unsigned fgm0 = 0u, fgm1 = 0u, validm = 0u;
#pragma unroll
      for (int j = 0; j < KROWS; j++) {
        fgm0 |= (c0[j] != 0 ? 1u : 0u) << j;
        fgm1 |= (c1[j] != 0 ? 1u : 0u) << j;
        int row = k0 + j;
        int gy = gy0 + row;
        if (xst && row >= RS && row < TH - RS && (unsigned)gy < 1024u)
          validm |= 1u << j;
      }

#pragma unroll
      for (int it = 0; it < RS; it++) {
        int pp = it & 1;
        Bex[pp][0][w][lane] = make_int2(c0[0], c1[0]);
        Bex[pp][1][w][lane] = make_int2(c0[KROWS - 1], c1[KROWS - 1]);
        __syncthreads();
        int2 ab = (w > 0) ? Bex[pp][1][w - 1][lane] : make_int2(0, 0);
        int2 bl = (w < 7) ? Bex[pp][0][w + 1][lane] : make_int2(0, 0);

        int a0 = ab.x, a1 = ab.y;         // row above (old)
        int b0 = c0[0], b1 = c1[0];       // current row (old)
#pragma unroll
        for (int j = 0; j < KROWS; j++) {
          int t0 = (j < KROWS - 1) ? c0[j + 1] : bl.x;  // row below (old)
          int t1 = (j < KROWS - 1) ? c1[j + 1] : bl.y;
          int vm0 = max(a0, max(b0, t0));
          int vm1 = max(a1, max(b1, t1));
          // lane-edge shfl garbage stays in the discarded halo
          int lft = __shfl_up_sync(0xffffffffu, vm1, 1);
          int rgt = __shfl_down_sync(0xffffffffu, vm0, 1);
          int m  = max(vm0, vm1);
          int h0 = max(lft, m);
          int h1 = max(m, rgt);
          int n0 = ((fgm0 >> j) & 1u) ? h0 : 0;
          int n1 = ((fgm1 >> j) & 1u) ? h1 : 0;
          if (it == RS - 1) {             // exact change detection, last step
            if (((validm >> j) & 1u) && ((n0 != c0[j]) || (n1 != c1[j]))) chg = 1u;
          }
          c0[j] = n0; c1[j] = n1;
          a0 = b0; a1 = b1; b0 = t0; b1 = t1;
        }
      }

      // store interior: cols 6..57 -> lanes 3..28; rows RS..TH-RS-1
      if (xst) {
#pragma unroll
        for (int j = 0; j < KROWS; j++) {
          int row = k0 + j;
          if (row < RS || row >= TH - RS) continue;
          int gy = gy0 + row;
          if ((unsigned)gy < 1024u)
            __stcg((int2*)(dst + base + ((unsigned)gy << 10) + (unsigned)gx),
                   make_int2(c0[j], c1[j]));
        }
      }
    }

    int any = __syncthreads_or((int)chg);
    if (threadIdx.x == 0 && any) atomicOr(&g_chgs[rnd], 1u);
    gsync();
    if (*(volatile unsigned*)&g_chgs[rnd] == 0u) break;  // global fixed point
  }

  if (blockIdx.x == 0 && threadIdx.x == 0)
    g_last = (unsigned)(rnd < 25 ? rnd : 24);
}

// ---------------------------------------------------------------------------
// distinct count: value v exists in final field iff px (v-1) holds label v
// (it is its component's max). distinct_fg = #{p : fin[p]==p+1}; bg separate.
// ---------------------------------------------------------------------------
__global__ void k_cc() {
  __shared__ int sc[8];
  const int* __restrict__ fin = (g_last & 1u) ? g_labA : g_labB;
  unsigned base = blockIdx.x * 4096u;
  unsigned t = base >> 22;
  int cnt = 0, zer = 0;
#pragma unroll
  for (int j = 0; j < 16; j++) {
    unsigned idx = base + threadIdx.x + (unsigned)j * 256u;
    int v = fin[idx];
    unsigned wt = idx & 0x3FFFFFu;
    cnt += (v == (int)(wt + 1u)) ? 1 : 0;
    zer |= (v == 0) ? 1 : 0;
  }
#pragma unroll
  for (int o = 16; o; o >>= 1) {
    cnt += __shfl_down_sync(0xffffffffu, cnt, o);
    zer |= __shfl_down_sync(0xffffffffu, zer, o);
  }
  int w = threadIdx.x >> 5;
  if ((threadIdx.x & 31) == 0) sc[w] = (cnt << 1) | zer;
  __syncthreads();
  if (threadIdx.x == 0) {
    int acc = sc[0];
    for (int i = 1; i < 8; i++) acc = (((acc >> 1) + (sc[i] >> 1)) << 1) | ((acc | sc[i]) & 1);
    atomicAdd(&g_cnt[t], (unsigned)(acc >> 1));
    if (acc & 1) atomicOr(&g_zf[t], 1u);
  }
}

// ---------------------------------------------------------------------------
// final scalar. distinct = cnt + [bg exists AND px0 is not a component max]
// (value 0 from bg collides with ref label 0 of a px0-max component)
// ---------------------------------------------------------------------------
__global__ void k_final(float* out) {
  if (threadIdx.x == 0 && blockIdx.x == 0) {
    const int* fin = (g_last & 1u) ? g_labA : g_labB;
    int c0 = (int)g_cnt[0] + ((g_zf[0] && fin[0] != 1) ? 1 : 0);
    int c1 = (int)g_cnt[1] + ((g_zf[1] && fin[4u << 20] != 1) ? 1 : 0);
    float ccs  = (float)c0;
    float ccsg = (float)c1;
    float nsg  = (float)g_cnt[2];
    out[0] = __fdiv_rn(fabsf(__fsub_rn(ccsg, ccs)), nsg);
  }
}

// ---------------------------------------------------------------------------
extern "C" void kernel_launch(void* const* d_in, const int* in_sizes, int n_in,
                              void* d_out, int out_size) {
  const float* img = (const float*)d_in[0];
  const float* lab = (const float*)d_in[1];
  float* out = (float*)d_out;

  k_init<<<1, 32>>>();
  k_open<<<dim3(1024 / OX, 1024 / OY, 8), 256>>>(img, lab);
  k_threshold<<<NPIX / 4096u, 256>>>();
  k_prop_all<<<NBLK, 256>>>();
  k_cc<<<NPIX / 4096u, 256>>>();
  k_final<<<1, 32>>>(out);
}

// round 10
// speedup vs baseline: 1.3731x; 1.3731x over previous
#include <cuda_runtime.h>

// ============================================================================
// Connect_Loss: opening(cross) -> global minmax norm -> binarize(0.5)
//   -> 150 iters of fg-masked 3x3 maxpool label propagation (exact)
//   -> count distinct labels -> |ccsg - ccs| / numSg  (scalar out)
// Shapes: img, lab: (4,1,1024,1024) fp32. 8 slices of 1024^2 total.
//
// Persistent propagation with per-tile convergence skipping (bit-exact):
// labels are monotone; a tile whose 9-neighbor cone saw no change last round
// reproduces its output exactly -> skip with zero work (both ping-pong
// buffers provably hold its fixed values). Global exit when a full round
// changes nothing anywhere. Distinct count via fin[p]==p+1 (component max).
// ============================================================================

#define NPIX  (8u << 20)            // 8,388,608 px total (2 tensors)

__device__ int   g_labA[NPIX];               // label ping
__device__ int   g_labB[NPIX];               // label pong (also float scratch: opened img)
__device__ unsigned int  g_red[4];           // mn0,mx0,mn1,mx1 as uint bits (nonneg floats)
__device__ unsigned int  g_cnt[4];           // distinct0, distinct1, numSg, unused
__device__ unsigned int  g_zf[2];            // background-exists flags
__device__ unsigned int  g_chgs[32];         // per-round "anything changed" flags
__device__ unsigned int  g_last;             // last round that actually ran
__device__ unsigned int  g_bar_cnt;          // barrier arrival counter
__device__ unsigned int  g_bar_gen;          // barrier generation
__device__ int           g_tflag[2][8][8][20]; // per-round-parity tile change flags

// ---------------------------------------------------------------------------
__global__ void k_init() {
  int tid = threadIdx.x;
  if (tid < 32) g_chgs[tid] = 0u;
  if (tid == 0) {
    g_red[0] = 0x7f800000u; g_red[1] = 0u;   // +inf / 0 (values are nonneg)
    g_red[2] = 0x7f800000u; g_red[3] = 0u;
    g_cnt[0] = 0u; g_cnt[1] = 0u; g_cnt[2] = 0u; g_cnt[3] = 0u;
    g_zf[0] = 0u; g_zf[1] = 0u;
    g_bar_cnt = 0u; g_last = 0u;
  }
}

// ---------------------------------------------------------------------------
// fused opening: erosion (min cross, +BIG pad) then dilation (max cross,
// -BIG pad), all in shared memory; stores opened value (float, into g_labB)
// and reduces per-tensor global min/max.
// ---------------------------------------------------------------------------
#define OX 64
#define OY 16

__global__ void __launch_bounds__(256) k_open(const float* __restrict__ img,
                                              const float* __restrict__ lab) {
  __shared__ float RAW[OY + 4][OX + 4];   // 20 x 68
  __shared__ float ER[OY + 2][OX + 4];    // 18 x 68 (66 used)
  __shared__ float smn[8], smx[8];

  unsigned s = blockIdx.z;
  const float* __restrict__ p = (s < 4u) ? (img + (s << 20)) : (lab + ((s - 4u) << 20));
  float* __restrict__ op = ((float*)g_labB) + (s << 20);

  int gx0 = (int)blockIdx.x * OX - 2;
  int gy0 = (int)blockIdx.y * OY - 2;
  int tid = threadIdx.x;

  for (int i = tid; i < (OY + 4) * (OX + 4); i += 256) {
    int ly = i / (OX + 4), lx = i - ly * (OX + 4);
    int gy = gy0 + ly, gx = gx0 + lx;
    float v = 1e30f;
    if ((unsigned)gy < 1024u && (unsigned)gx < 1024u)
      v = p[((unsigned)gy << 10) + (unsigned)gx];
    RAW[ly][lx] = v;
  }
  __syncthreads();

  for (int i = tid; i < (OY + 2) * (OX + 2); i += 256) {
    int ey = i / (OX + 2), ex = i - ey * (OX + 2);
    int gy = gy0 + 1 + ey, gx = gx0 + 1 + ex;
    float v = -1e30f;
    if ((unsigned)gy < 1024u && (unsigned)gx < 1024u) {
      v = RAW[ey + 1][ex + 1];
      v = fminf(v, RAW[ey][ex + 1]);
      v = fminf(v, RAW[ey + 2][ex + 1]);
      v = fminf(v, RAW[ey + 1][ex]);
      v = fminf(v, RAW[ey + 1][ex + 2]);
    }
    ER[ey][ex] = v;
  }
  __syncthreads();

  int ox = tid & 63;
  int oyb = tid >> 6;
  float mn = 3.4e38f, mx = -3.4e38f;
#pragma unroll
  for (int k = 0; k < 4; k++) {
    int oy = oyb + 4 * k;
    float v = ER[oy + 1][ox + 1];
    v = fmaxf(v, ER[oy][ox + 1]);
    v = fmaxf(v, ER[oy + 2][ox + 1]);
    v = fmaxf(v, ER[oy + 1][ox]);
    v = fmaxf(v, ER[oy + 1][ox + 2]);
    int gy = gy0 + 2 + oy, gx = gx0 + 2 + ox;
    op[((unsigned)gy << 10) + (unsigned)gx] = v;
    mn = fminf(mn, v);
    mx = fmaxf(mx, v);
  }
#pragma unroll
  for (int o = 16; o; o >>= 1) {
    mn = fminf(mn, __shfl_down_sync(0xffffffffu, mn, o));
    mx = fmaxf(mx, __shfl_down_sync(0xffffffffu, mx, o));
  }
  int w = tid >> 5;
  if ((tid & 31) == 0) { smn[w] = mn; smx[w] = mx; }
  __syncthreads();
  if (tid == 0) {
    for (int i = 1; i < 8; i++) { mn = fminf(mn, smn[i]); mx = fmaxf(mx, smx[i]); }
    unsigned t = s >> 2;
    atomicMin(&g_red[t * 2u],     __float_as_uint(mn));
    atomicMax(&g_red[t * 2u + 1], __float_as_uint(mx));
  }
}

// ---------------------------------------------------------------------------
// threshold: fg = ((op - mn) / ((mx - mn) + 1e-10)) >= 0.5  (IEEE fp32 div)
// ---------------------------------------------------------------------------
__global__ void k_threshold() {
  __shared__ int sc[8];
  const float* __restrict__ op = (const float*)g_labB;
  unsigned base = blockIdx.x * 4096u;
  unsigned t = base >> 22;
  float mn = __uint_as_float(g_red[t * 2u]);
  float mx = __uint_as_float(g_red[t * 2u + 1]);
  float d  = __fadd_rn(__fsub_rn(mx, mn), 1e-10f);
  int cnt = 0;
#pragma unroll
  for (int j = 0; j < 16; j++) {
    unsigned idx = base + threadIdx.x + (unsigned)j * 256u;
    float v = op[idx];
    bool fg = (__fdiv_rn(__fsub_rn(v, mn), d) >= 0.5f);
    unsigned wt = idx & 0x3FFFFFu;          // tensor-local index
    g_labA[idx] = fg ? (int)(wt + 1u) : 0;
    cnt += (fg ? 1 : 0);
  }
  if (t == 1u) {
#pragma unroll
    for (int o = 16; o; o >>= 1) cnt += __shfl_down_sync(0xffffffffu, cnt, o);
    int w = threadIdx.x >> 5;
    if ((threadIdx.x & 31) == 0) sc[w] = cnt;
    __syncthreads();
    if (threadIdx.x == 0) {
      for (int i = 1; i < 8; i++) cnt += sc[i];
      atomicAdd(&g_cnt[2], (unsigned)cnt);
    }
  }
}

// ---------------------------------------------------------------------------
// persistent propagation. Tile 64x144, 8 warps x (2 cols x 18 rows) in regs.
// One launch; software global barrier per round; per-tile skip; exact exit.
// ---------------------------------------------------------------------------
#define TW 64
#define TH 144
#define KROWS 18
#define RS 6
#define IW (TW - 2 * RS)   // 52
#define IH (TH - 2 * RS)   // 132
#define NTILE 1280         // 8 slices x 8 ty x 20 tx
#define NBLK 444           // 148 SMs x 3 blocks (co-resident at <=85 regs)

__device__ __forceinline__ void gsync() {
  __syncthreads();
  if (threadIdx.x == 0) {
    __threadfence();
    volatile unsigned* vg = &g_bar_gen;
    unsigned gen = *vg;
    if (atomicAdd(&g_bar_cnt, 1u) == NBLK - 1u) {
      atomicExch(&g_bar_cnt, 0u);
      __threadfence();
      *vg = gen + 1u;
    } else {
      while (*vg == gen) { }
      __threadfence();
    }
  }
  __syncthreads();
}

__global__ void __launch_bounds__(256, 3) k_prop_all() {
  __shared__ int2 Bex[2][2][8][32];  // [parity][top/bot][warpRow][lane]
  int lane = threadIdx.x & 31;
  int w    = threadIdx.x >> 5;
  int k0   = w * KROWS;

  int rnd;
  for (rnd = 0; rnd < 25; rnd++) {       // 25 * RS(6) = 150 exact steps max
    int flip = rnd & 1;
    const int* __restrict__ src = flip ? g_labB : g_labA;
    int* __restrict__ dst = flip ? g_labA : g_labB;
    int roundAny = 0;

    for (unsigned t = blockIdx.x; t < NTILE; t += NBLK) {
      unsigned s  = t / 160u;
      unsigned rr = t - s * 160u;
      unsigned ty = rr / 20u;
      unsigned tx = rr - ty * 20u;

      // activity: active iff round 0 or any cone-neighbor tile changed last round
      int act = (rnd == 0) ? 1 : 0;
      if (!act) {
        const int (*pf)[20] = g_tflag[(rnd - 1) & 1][s];
        int ylo = (ty > 0) ? (int)ty - 1 : 0, yhi = (ty < 7) ? (int)ty + 1 : 7;
        int xlo = (tx > 0) ? (int)tx - 1 : 0, xhi = (tx < 19) ? (int)tx + 1 : 19;
        for (int yy = ylo; yy <= yhi; yy++)
          for (int xx = xlo; xx <= xhi; xx++)
            act |= __ldcg(&pf[yy][xx]);
      }
      if (!act) {   // skipped tile: fixed values, identical in both buffers
        if (threadIdx.x == 0) __stcg(&g_tflag[flip][s][ty][tx], 0);
        continue;
      }

      unsigned base = s << 20;
      int gx0 = (int)tx * IW - RS;
      int gy0 = (int)ty * IH - RS;
      int gx  = gx0 + 2 * lane;           // even; pairs never straddle 1024
      bool xin = (gx >= 0) && (gx <= 1022);
      bool xst = xin && (lane >= 3) && (lane <= 28);

      int c0[KROWS], c1[KROWS];
#pragma unroll
      for (int j = 0; j < KROWS; j++) {
        int gy = gy0 + k0 + j;
        int2 v = make_int2(0, 0);         // OOB -> 0 == background
        if (xin && (unsigned)gy < 1024u)
          v = __ldcg((const int2*)(src + base + ((unsigned)gy << 10) + (unsigned)gx));
        c0[j] = v.x; c1[j] = v.y;
      }

      unsigned fgm0 = 0u, fgm1 = 0u, validm = 0u;
#pragma unroll
      for (int j = 0; j < KROWS; j++) {
        fgm0 |= (c0[j] != 0 ? 1u : 0u) << j;
        fgm1 |= (c1[j] != 0 ? 1u : 0u) << j;
        int row = k0 + j;
        int gy = gy0 + row;
        if (xst && row >= RS && row < TH - RS && (unsigned)gy < 1024u)
          validm |= 1u << j;
      }

      unsigned chg = 0u;
#pragma unroll
      for (int it = 0; it < RS; it++) {
        int pp = it & 1;
        Bex[pp][0][w][lane] = make_int2(c0[0], c1[0]);
        Bex[pp][1][w][lane] = make_int2(c0[KROWS - 1], c1[KROWS - 1]);
        __syncthreads();
        int2 ab = (w > 0) ? Bex[pp][1][w - 1][lane] : make_int2(0, 0);
        int2 bl = (w < 7) ? Bex[pp][0][w + 1][lane] : make_int2(0, 0);

        int a0 = ab.x, a1 = ab.y;         // row above (old)
        int b0 = c0[0], b1 = c1[0];       // current row (old)
#pragma unroll
        for (int j = 0; j < KROWS; j++) {
          int t0 = (j < KROWS - 1) ? c0[j + 1] : bl.x;  // row below (old)
          int t1 = (j < KROWS - 1) ? c1[j + 1] : bl.y;
          int vm0 = max(a0, max(b0, t0));
          int vm1 = max(a1, max(b1, t1));
          // lane-edge shfl garbage stays in the discarded halo
          int lft = __shfl_up_sync(0xffffffffu, vm1, 1);
          int rgt = __shfl_down_sync(0xffffffffu, vm0, 1);
          int m  = max(vm0, vm1);
          int h0 = max(lft, m);
          int h1 = max(m, rgt);
          int n0 = ((fgm0 >> j) & 1u) ? h0 : 0;
          int n1 = ((fgm1 >> j) & 1u) ? h1 : 0;
          // whole-round change detection (monotone: no change-back possible)
          if (((validm >> j) & 1u) && ((n0 != c0[j]) || (n1 != c1[j]))) chg = 1u;
          c0[j] = n0; c1[j] = n1;
          a0 = b0; a1 = b1; b0 = t0; b1 = t1;
        }
      }

      // store interior: cols 6..57 -> lanes 3..28; rows RS..TH-RS-1
      if (xst) {
#pragma unroll
        for (int j = 0; j < KROWS; j++) {
          int row = k0 + j;
          if (row < RS || row >= TH - RS) continue;
          int gy = gy0 + row;
          if ((unsigned)gy < 1024u)
            __stcg((int2*)(dst + base + ((unsigned)gy << 10) + (unsigned)gx),
                   make_int2(c0[j], c1[j]));
        }
      }

      int tchg = __syncthreads_or((int)chg);
      if (threadIdx.x == 0) __stcg(&g_tflag[flip][s][ty][tx], tchg ? 1 : 0);
      roundAny |= tchg;
    }

    if (threadIdx.x == 0 && roundAny) atomicOr(&g_chgs[rnd], 1u);
    gsync();
    if (*(volatile unsigned*)&g_chgs[rnd] == 0u) break;  // global fixed point
  }

  if (blockIdx.x == 0 && threadIdx.x == 0)
    g_last = (unsigned)(rnd < 25 ? rnd : 24);
}

// ---------------------------------------------------------------------------
// distinct count: value v exists in final field iff px (v-1) holds label v
// (it is its component's max). distinct_fg = #{p : fin[p]==p+1}; bg separate.
// ---------------------------------------------------------------------------
__global__ void k_cc() {
  __shared__ int sc[8];
  const int* __restrict__ fin = (g_last & 1u) ? g_labA : g_labB;
  unsigned base = blockIdx.x * 4096u;
  unsigned t = base >> 22;
  int cnt = 0, zer = 0;
#pragma unroll
  for (int j = 0; j < 16; j++) {
    unsigned idx = base + threadIdx.x + (unsigned)j * 256u;
    int v = fin[idx];
    unsigned wt = idx & 0x3FFFFFu;
    cnt += (v == (int)(wt + 1u)) ? 1 : 0;
    zer |= (v == 0) ? 1 : 0;
  }
#pragma unroll
  for (int o = 16; o; o >>= 1) {
    cnt += __shfl_down_sync(0xffffffffu, cnt, o);
    zer |= __shfl_down_sync(0xffffffffu, zer, o);
  }
  int w = threadIdx.x >> 5;
  if ((threadIdx.x & 31) == 0) sc[w] = (cnt << 1) | zer;
  __syncthreads();
  if (threadIdx.x == 0) {
    int acc = sc[0];
    for (int i = 1; i < 8; i++) acc = (((acc >> 1) + (sc[i] >> 1)) << 1) | ((acc | sc[i]) & 1);
    atomicAdd(&g_cnt[t], (unsigned)(acc >> 1));
    if (acc & 1) atomicOr(&g_zf[t], 1u);
  }
}

// ---------------------------------------------------------------------------
// final scalar. distinct = cnt + [bg exists AND px0 is not a component max]
// ---------------------------------------------------------------------------
__global__ void k_final(float* out) {
  if (threadIdx.x == 0 && blockIdx.x == 0) {
    const int* fin = (g_last & 1u) ? g_labA : g_labB;
    int c0 = (int)g_cnt[0] + ((g_zf[0] && fin[0] != 1) ? 1 : 0);
    int c1 = (int)g_cnt[1] + ((g_zf[1] && fin[4u << 20] != 1) ? 1 : 0);
    float ccs  = (float)c0;
    float ccsg = (float)c1;
    float nsg  = (float)g_cnt[2];
    out[0] = __fdiv_rn(fabsf(__fsub_rn(ccsg, ccs)), nsg);
  }
}

// ---------------------------------------------------------------------------
extern "C" void kernel_launch(void* const* d_in, const int* in_sizes, int n_in,
                              void* d_out, int out_size) {
  const float* img = (const float*)d_in[0];
  const float* lab = (const float*)d_in[1];
  float* out = (float*)d_out;

  k_init<<<1, 32>>>();
  k_open<<<dim3(1024 / OX, 1024 / OY, 8), 256>>>(img, lab);
  k_threshold<<<NPIX / 4096u, 256>>>();
  k_prop_all<<<NBLK, 256>>>();
  k_cc<<<NPIX / 4096u, 256>>>();
  k_final<<<1, 32>>>(out);
}

// round 12
// speedup vs baseline: 1.4162x; 1.0314x over previous
#include <cuda_runtime.h>

// ============================================================================
// Connect_Loss: opening(cross) -> global minmax norm -> binarize(0.5)
//   -> 150 iters of fg-masked 3x3 maxpool label propagation (exact)
//   -> count distinct labels -> |ccsg - ccs| / numSg  (scalar out)
// Shapes: img, lab: (4,1,1024,1024) fp32. 8 slices of 1024^2 total.
//
// Persistent propagation, 4 cols/lane + DPX max3, per-tile skip (monotone,
// final-vs-initial change detection), threshold fused into round 0, distinct
// count fused into the kernel tail. All bit-exact vs 150 Jacobi steps.
// ============================================================================

#define NPIX  (8u << 20)            // 8,388,608 px total (2 tensors)

__device__ int   g_labA[NPIX];               // label ping (round 0,2,4,... output)
__device__ int   g_labB[NPIX];               // label pong; float scratch: opened img
__device__ unsigned int  g_red[4];           // mn0,mx0,mn1,mx1 as uint bits (nonneg)
__device__ unsigned int  g_cnt[4];           // distinct0, distinct1, numSg
__device__ unsigned int  g_zf[2];            // background-exists flags
__device__ unsigned int  g_chgs[32];         // per-round "anything changed"
__device__ unsigned int  g_last;             // last executed round
__device__ unsigned int  g_bar_cnt;          // barrier arrival counter
__device__ unsigned int  g_bar_gen;          // barrier generation
__device__ int           g_tflag[2][8][16][10]; // per-parity tile change flags

__device__ __forceinline__ int max3i(int a, int b, int c) {
  return __vimax3_s32(a, b, c);
}

// ---------------------------------------------------------------------------
__global__ void k_init() {
  int tid = threadIdx.x;
  if (tid < 32) g_chgs[tid] = 0u;
  if (tid == 0) {
    g_red[0] = 0x7f800000u; g_red[1] = 0u;
    g_red[2] = 0x7f800000u; g_red[3] = 0u;
    g_cnt[0] = 0u; g_cnt[1] = 0u; g_cnt[2] = 0u; g_cnt[3] = 0u;
    g_zf[0] = 0u; g_zf[1] = 0u;
    g_bar_cnt = 0u; g_last = 0u;
  }
}

// ---------------------------------------------------------------------------
// fused opening in smem; stores opened float (into g_labB) + min/max reduce
// ---------------------------------------------------------------------------
#define OX 64
#define OY 16

__global__ void __launch_bounds__(256) k_open(const float* __restrict__ img,
                                              const float* __restrict__ lab) {
  __shared__ float RAW[OY + 4][OX + 4];
  __shared__ float ER[OY + 2][OX + 4];
  __shared__ float smn[8], smx[8];

  unsigned s = blockIdx.z;
  const float* __restrict__ p = (s < 4u) ? (img + (s << 20)) : (lab + ((s - 4u) << 20));
  float* __restrict__ op = ((float*)g_labB) + (s << 20);

  int gx0 = (int)blockIdx.x * OX - 2;
  int gy0 = (int)blockIdx.y * OY - 2;
  int tid = threadIdx.x;

  for (int i = tid; i < (OY + 4) * (OX + 4); i += 256) {
    int ly = i / (OX + 4), lx = i - ly * (OX + 4);
    int gy = gy0 + ly, gx = gx0 + lx;
    float v = 1e30f;
    if ((unsigned)gy < 1024u && (unsigned)gx < 1024u)
      v = p[((unsigned)gy << 10) + (unsigned)gx];
    RAW[ly][lx] = v;
  }
  __syncthreads();

  for (int i = tid; i < (OY + 2) * (OX + 2); i += 256) {
    int ey = i / (OX + 2), ex = i - ey * (OX + 2);
    int gy = gy0 + 1 + ey, gx = gx0 + 1 + ex;
    float v = -1e30f;
    if ((unsigned)gy < 1024u && (unsigned)gx < 1024u) {
      v = RAW[ey + 1][ex + 1];
      v = fminf(v, RAW[ey][ex + 1]);
      v = fminf(v, RAW[ey + 2][ex + 1]);
      v = fminf(v, RAW[ey + 1][ex]);
      v = fminf(v, RAW[ey + 1][ex + 2]);
    }
    ER[ey][ex] = v;
  }
  __syncthreads();

  int ox = tid & 63;
  int oyb = tid >> 6;
  float mn = 3.4e38f, mx = -3.4e38f;
#pragma unroll
  for (int k = 0; k < 4; k++) {
    int oy = oyb + 4 * k;
    float v = ER[oy + 1][ox + 1];
    v = fmaxf(v, ER[oy][ox + 1]);
    v = fmaxf(v, ER[oy + 2][ox + 1]);
    v = fmaxf(v, ER[oy + 1][ox]);
    v = fmaxf(v, ER[oy + 1][ox + 2]);
    int gy = gy0 + 2 + oy, gx = gx0 + 2 + ox;
    op[((unsigned)gy << 10) + (unsigned)gx] = v;
    mn = fminf(mn, v);
    mx = fmaxf(mx, v);
  }
#pragma unroll
  for (int o = 16; o; o >>= 1) {
    mn = fminf(mn, __shfl_down_sync(0xffffffffu, mn, o));
    mx = fmaxf(mx, __shfl_down_sync(0xffffffffu, mx, o));
  }
  int w = tid >> 5;
  if ((tid & 31) == 0) { smn[w] = mn; smx[w] = mx; }
  __syncthreads();
  if (tid == 0) {
    for (int i = 1; i < 8; i++) { mn = fminf(mn, smn[i]); mx = fmaxf(mx, smx[i]); }
    unsigned t = s >> 2;
    atomicMin(&g_red[t * 2u],     __float_as_uint(mn));
    atomicMax(&g_red[t * 2u + 1], __float_as_uint(mx));
  }
}

// ---------------------------------------------------------------------------
// persistent propagation. Tile 128x80: 8 warps x (KR=10 rows), 4 cols/lane.
// Round 0 fuses thresholding (labels from opened floats) + numSg count.
// Rounds: RS=6 exact Jacobi steps; per-tile skip; global early exit.
// Tail: fused distinct-label count.
// ---------------------------------------------------------------------------
#define TW 128
#define KR 10
#define TH 80              // 8*KR
#define RS 6
#define HX 8               // x halo (>= RS, keeps int4 alignment)
#define IW (TW - 2 * HX)   // 112
#define IH (TH - 2 * RS)   // 68
#define NXT 10             // ceil(1024/112)
#define NYT 16             // ceil(1024/68)
#define NTILE (NXT * NYT * 8)   // 1280
#define NBLK 444           // 148 SMs x 3 blocks co-resident

__device__ __forceinline__ void gsync() {
  __syncthreads();
  if (threadIdx.x == 0) {
    __threadfence();
    volatile unsigned* vg = &g_bar_gen;
    unsigned gen = *vg;
    if (atomicAdd(&g_bar_cnt, 1u) == NBLK - 1u) {
      atomicExch(&g_bar_cnt, 0u);
      __threadfence();
      *vg = gen + 1u;
    } else {
      while (*vg == gen) { }
      __threadfence();
    }
  }
  __syncthreads();
}

__global__ void __launch_bounds__(256, 3) k_prop_all() {
  __shared__ int4 Bex[2][2][8][32];   // [parity][top/bot][warp][lane]
  __shared__ int sred[8];
  int lane = threadIdx.x & 31;
  int w    = threadIdx.x >> 5;
  int k0   = w * KR;

  int nsg = 0;
  int rnd;
  for (rnd = 0; rnd < 25; rnd++) {        // 25 * RS = 150 exact steps max
    // round r output: r even -> A, r odd -> B. round>=1 input = prev output.
    int* __restrict__ dst = (rnd & 1) ? g_labB : g_labA;
    const int* __restrict__ src = (rnd & 1) ? g_labA : g_labB; // r>=1 only
    int roundAny = (rnd == 0) ? 1 : 0;

    for (unsigned t = blockIdx.x; t < NTILE; t += NBLK) {
      unsigned s  = t / (NXT * NYT);
      unsigned rr = t - s * (NXT * NYT);
      unsigned ty = rr / NXT;
      unsigned tx = rr - ty * NXT;

      if (rnd > 0) {  // activity: any cone-neighbor changed last round?
        int act = 0;
        const int (*pf)[NXT] = g_tflag[(rnd - 1) & 1][s];
        int ylo = (ty > 0) ? (int)ty - 1 : 0, yhi = (ty < NYT - 1) ? (int)ty + 1 : NYT - 1;
        int xlo = (tx > 0) ? (int)tx - 1 : 0, xhi = (tx < NXT - 1) ? (int)tx + 1 : NXT - 1;
        for (int yy = ylo; yy <= yhi; yy++)
          for (int xx = xlo; xx <= xhi; xx++)
            act |= __ldcg(&pf[yy][xx]);
        if (!act) {   // fixed tile: identical in both buffers, zero work
          if (threadIdx.x == 0) __stcg(&g_tflag[rnd & 1][s][ty][tx], 0);
          continue;
        }
      }

      unsigned base = s << 20;
      int gx0 = (int)tx * IW - HX;
      int gy0 = (int)ty * IH - RS;
      int gx  = gx0 + 4 * lane;           // multiple of 4 -> int4 aligned
      bool xin = (gx >= 0) && (gx <= 1020);
      bool xst = xin && (lane >= 2) && (lane <= 29);

      int c0[KR], c1[KR], c2[KR], c3[KR];

      if (rnd == 0) {
        // fused threshold: labels from opened floats
        unsigned tt = s >> 2;
        float mnv = __uint_as_float(g_red[tt * 2u]);
        float mxv = __uint_as_float(g_red[tt * 2u + 1]);
        float dv  = __fadd_rn(__fsub_rn(mxv, mnv), 1e-10f);
        const float* __restrict__ opf = ((const float*)g_labB) + base;
        unsigned lbase = (s & 3u) << 20;
#pragma unroll
        for (int j = 0; j < KR; j++) {
          int gy = gy0 + k0 + j;
          int l0 = 0, l1 = 0, l2 = 0, l3 = 0;
          if (xin && (unsigned)gy < 1024u) {
            float4 f = *(const float4*)(opf + (((unsigned)gy) << 10) + (unsigned)gx);
            unsigned li = lbase + (((unsigned)gy) << 10) + (unsigned)gx;
            if (__fdiv_rn(__fsub_rn(f.x, mnv), dv) >= 0.5f) l0 = (int)(li + 1u);
            if (__fdiv_rn(__fsub_rn(f.y, mnv), dv) >= 0.5f) l1 = (int)(li + 2u);
            if (__fdiv_rn(__fsub_rn(f.z, mnv), dv) >= 0.5f) l2 = (int)(li + 3u);
            if (__fdiv_rn(__fsub_rn(f.w, mnv), dv) >= 0.5f) l3 = (int)(li + 4u);
          }
          c0[j] = l0; c1[j] = l1; c2[j] = l2; c3[j] = l3;
        }
      } else {
#pragma unroll
        for (int j = 0; j < KR; j++) {
          int gy = gy0 + k0 + j;
          int4 v = make_int4(0, 0, 0, 0);
          if (xin && (unsigned)gy < 1024u)
            v = __ldcg((const int4*)(src + base + (((unsigned)gy) << 10) + (unsigned)gx));
          c0[j] = v.x; c1[j] = v.y; c2[j] = v.z; c3[j] = v.w;
        }
      }

      unsigned f0 = 0u, f1 = 0u, f2 = 0u, f3 = 0u, validm = 0u;
#pragma unroll
      for (int j = 0; j < KR; j++) {
        f0 |= (c0[j] != 0 ? 1u : 0u) << j;
        f1 |= (c1[j] != 0 ? 1u : 0u) << j;
        f2 |= (c2[j] != 0 ? 1u : 0u) << j;
        f3 |= (c3[j] != 0 ? 1u : 0u) << j;
        int row = k0 + j;
        int gy = gy0 + row;
        if (xst && row >= RS && row < TH - RS && (unsigned)gy < 1024u)
          validm |= 1u << j;
      }

      if (rnd == 0 && s >= 4u) {          // numSg on interior px of lab
#pragma unroll
        for (int j = 0; j < KR; j++)
          if ((validm >> j) & 1u)
            nsg += ((f0 >> j) & 1) + ((f1 >> j) & 1) + ((f2 >> j) & 1) + ((f3 >> j) & 1);
      }

      for (int it = 0; it < RS; it++) {
        int pp = it & 1;
        Bex[pp][0][w][lane] = make_int4(c0[0], c1[0], c2[0], c3[0]);
        Bex[pp][1][w][lane] = make_int4(c0[KR - 1], c1[KR - 1], c2[KR - 1], c3[KR - 1]);
        __syncthreads();
        int4 ab = (w > 0) ? Bex[pp][1][w - 1][lane] : make_int4(0, 0, 0, 0);
        int4 bl = (w < 7) ? Bex[pp][0][w + 1][lane] : make_int4(0, 0, 0, 0);

        int a0 = ab.x, a1 = ab.y, a2 = ab.z, a3 = ab.w;
        int b0 = c0[0], b1 = c1[0], b2 = c2[0], b3 = c3[0];
#pragma unroll
        for (int j = 0; j < KR; j++) {
          int t0 = (j < KR - 1) ? c0[j + 1] : bl.x;
          int t1 = (j < KR - 1) ? c1[j + 1] : bl.y;
          int t2 = (j < KR - 1) ? c2[j + 1] : bl.z;
          int t3 = (j < KR - 1) ? c3[j + 1] : bl.w;
          int v0 = max3i(a0, b0, t0);
          int v1 = max3i(a1, b1, t1);
          int v2 = max3i(a2, b2, t2);
          int v3 = max3i(a3, b3, t3);
          // lane-edge shfl garbage stays in the discarded halo
          int lft = __shfl_up_sync(0xffffffffu, v3, 1);
          int rgt = __shfl_down_sync(0xffffffffu, v0, 1);
          c0[j] = ((f0 >> j) & 1u) ? max3i(lft, v0, v1) : 0;
          c1[j] = ((f1 >> j) & 1u) ? max3i(v0, v1, v2) : 0;
          c2[j] = ((f2 >> j) & 1u) ? max3i(v1, v2, v3) : 0;
          c3[j] = ((f3 >> j) & 1u) ? max3i(v2, v3, rgt) : 0;
          a0 = b0; a1 = b1; a2 = b2; a3 = b3;
          b0 = t0; b1 = t1; b2 = t2; b3 = t3;
        }
      }

      // store interior; rounds>=1: change = final != initial (monotone)
      unsigned diff = 0u;
#pragma unroll
      for (int j = 0; j < KR; j++) {
        if (!((validm >> j) & 1u)) continue;
        int gy = gy0 + k0 + j;
        unsigned off = base + (((unsigned)gy) << 10) + (unsigned)gx;
        if (rnd > 0) {
          int4 o = __ldcg((const int4*)(src + off));
          diff |= (unsigned)((o.x ^ c0[j]) | (o.y ^ c1[j]) | (o.z ^ c2[j]) | (o.w ^ c3[j]));
        }
        __stcg((int4*)(dst + off), make_int4(c0[j], c1[j], c2[j], c3[j]));
      }

      int tchg = __syncthreads_or((int)(diff != 0u)) || (rnd == 0);
      if (threadIdx.x == 0) __stcg(&g_tflag[rnd & 1][s][ty][tx], tchg ? 1 : 0);
      roundAny |= tchg;
    }

    if (rnd == 0) {                       // block-reduce numSg once
#pragma unroll
      for (int o = 16; o; o >>= 1) nsg += __shfl_down_sync(0xffffffffu, nsg, o);
      if (lane == 0) sred[w] = nsg;
      __syncthreads();
      if (threadIdx.x == 0) {
        int acc = 0;
        for (int i = 0; i < 8; i++) acc += sred[i];
        if (acc) atomicAdd(&g_cnt[2], (unsigned)acc);
      }
    }

    if (threadIdx.x == 0 && roundAny) atomicOr(&g_chgs[rnd], 1u);
    gsync();
    if (*(volatile unsigned*)&g_chgs[rnd] == 0u) break;  // global fixed point
  }

  int lastr = (rnd < 25) ? rnd : 24;
  if (blockIdx.x == 0 && threadIdx.x == 0) g_last = (unsigned)lastr;

  // ---- fused distinct count: v present iff px (v-1) holds label v ----
  const int* __restrict__ fin = (lastr & 1) ? g_labB : g_labA;
  int cnt0 = 0, cnt1 = 0, zer0 = 0, zer1 = 0;
  for (unsigned q = blockIdx.x * 256u + threadIdx.x; q < NPIX / 4u; q += NBLK * 256u) {
    unsigned idx = q * 4u;
    int4 v = __ldcg((const int4*)(fin + idx));
    int wt = (int)(idx & 0x3FFFFFu);
    int m = (v.x == wt + 1) + (v.y == wt + 2) + (v.z == wt + 3) + (v.w == wt + 4);
    int z = (v.x == 0) | (v.y == 0) | (v.z == 0) | (v.w == 0);
    int tt = (int)(idx >> 22);
    cnt0 += m & (tt ^ 1 ? -1 : 0) ? 0 : 0;  // (placeholder, replaced below)
    if (tt) { cnt1 += m; zer1 |= z; } else { cnt0 += m; zer0 |= z; }
  }
#pragma unroll
  for (int o = 16; o; o >>= 1) {
    cnt0 += __shfl_down_sync(0xffffffffu, cnt0, o);
    cnt1 += __shfl_down_sync(0xffffffffu, cnt1, o);
    zer0 |= __shfl_down_sync(0xffffffffu, zer0, o);
    zer1 |= __shfl_down_sync(0xffffffffu, zer1, o);
  }
  __syncthreads();   // sred reuse
  if (lane == 0) sred[w] = cnt0;
  __syncthreads();
  if (threadIdx.x == 0) {
    int a = 0; for (int i = 0; i < 8; i++) a += sred[i];
    if (a) atomicAdd(&g_cnt[0], (unsigned)a);
  }
  __syncthreads();
  if (lane == 0) sred[w] = cnt1;
  __syncthreads();
  if (threadIdx.x == 0) {
    int a = 0; for (int i = 0; i < 8; i++) a += sred[i];
    if (a) atomicAdd(&g_cnt[1], (unsigned)a);
  }
  if (lane == 0) {
    if (zer0) atomicOr(&g_zf[0], 1u);
    if (zer1) atomicOr(&g_zf[1], 1u);
  }
}

// ---------------------------------------------------------------------------
// final scalar. distinct = cnt + [bg exists AND px0 is not a component max]
// ---------------------------------------------------------------------------
__global__ void k_final(float* out) {
  if (threadIdx.x == 0 && blockIdx.x == 0) {
    const int* fin = (g_last & 1u) ? g_labB : g_labA;
    int c0 = (int)g_cnt[0] + ((g_zf[0] && fin[0] != 1) ? 1 : 0);
    int c1 = (int)g_cnt[1] + ((g_zf[1] && fin[4u << 20] != 1) ? 1 : 0);
    float ccs  = (float)c0;
    float ccsg = (float)c1;
    float nsg  = (float)g_cnt[2];
    out[0] = __fdiv_rn(fabsf(__fsub_rn(ccsg, ccs)), nsg);
  }
}

// ---------------------------------------------------------------------------
extern "C" void kernel_launch(void* const* d_in, const int* in_sizes, int n_in,
                              void* d_out, int out_size) {
  const float* img = (const float*)d_in[0];
  const float* lab = (const float*)d_in[1];
  float* out = (float*)d_out;

  k_init<<<1, 32>>>();
  k_open<<<dim3(1024 / OX, 1024 / OY, 8), 256>>>(img, lab);
  k_prop_all<<<NBLK, 256>>>();
  k_final<<<1, 32>>>(out);
}

// round 13
// speedup vs baseline: 1.4185x; 1.0016x over previous
#include <cuda_runtime.h>

// ============================================================================
// Connect_Loss: opening(cross) -> global minmax norm -> binarize(0.5)
//   -> 150 iters of fg-masked 3x3 maxpool label propagation (exact)
//   -> count distinct labels -> |ccsg - ccs| / numSg  (scalar out)
// Shapes: img, lab: (4,1,1024,1024) fp32. 8 slices of 1024^2 total.
//
// Persistent propagation: 19 rounds (18x8 + 1x6 = 150 steps exact), 4
// cols/lane + DPX max3, per-tile skip via cone-neighbor flags, change
// detection via 64-bit interior label sums (monotone => sum equal <=> no
// change), threshold fused into round 0, distinct count + final scalar
// fused into the kernel tail. All bit-exact vs 150 Jacobi steps.
// ============================================================================

#define NPIX  (8u << 20)            // 8,388,608 px total (2 tensors)

__device__ int   g_labA[NPIX];               // label ping (round 0,2,... output)
__device__ int   g_labB[NPIX];               // label pong; float scratch: opened img
__device__ unsigned int  g_red[4];           // mn0,mx0,mn1,mx1 as uint bits (nonneg)
__device__ unsigned int  g_cnt[4];           // distinct0, distinct1, numSg
__device__ unsigned int  g_zf[2];            // background-exists flags
__device__ unsigned int  g_chgs[32];         // per-round "anything changed"
__device__ unsigned int  g_bar_cnt;          // barrier arrival counter
__device__ unsigned int  g_bar_gen;          // barrier generation
__device__ int                    g_tflag[2][8][16][10]; // per-parity tile flags
__device__ unsigned long long     g_tsum[8][16][10];     // per-tile interior sums

__device__ __forceinline__ int max3i(int a, int b, int c) {
  return __vimax3_s32(a, b, c);
}

// ---------------------------------------------------------------------------
__global__ void k_init() {
  int tid = threadIdx.x;
  if (tid < 32) g_chgs[tid] = 0u;
  if (tid == 0) {
    g_red[0] = 0x7f800000u; g_red[1] = 0u;
    g_red[2] = 0x7f800000u; g_red[3] = 0u;
    g_cnt[0] = 0u; g_cnt[1] = 0u; g_cnt[2] = 0u; g_cnt[3] = 0u;
    g_zf[0] = 0u; g_zf[1] = 0u;
    g_bar_cnt = 0u;
  }
}

// ---------------------------------------------------------------------------
// fused opening in smem; stores opened float (into g_labB) + min/max reduce
// ---------------------------------------------------------------------------
#define OX 64
#define OY 16

__global__ void __launch_bounds__(256) k_open(const float* __restrict__ img,
                                              const float* __restrict__ lab) {
  __shared__ float RAW[OY + 4][OX + 4];
  __shared__ float ER[OY + 2][OX + 4];
  __shared__ float smn[8], smx[8];

  unsigned s = blockIdx.z;
  const float* __restrict__ p = (s < 4u) ? (img + (s << 20)) : (lab + ((s - 4u) << 20));
  float* __restrict__ op = ((float*)g_labB) + (s << 20);

  int gx0 = (int)blockIdx.x * OX - 2;
  int gy0 = (int)blockIdx.y * OY - 2;
  int tid = threadIdx.x;

  for (int i = tid; i < (OY + 4) * (OX + 4); i += 256) {
    int ly = i / (OX + 4), lx = i - ly * (OX + 4);
    int gy = gy0 + ly, gx = gx0 + lx;
    float v = 1e30f;
    if ((unsigned)gy < 1024u && (unsigned)gx < 1024u)
      v = p[((unsigned)gy << 10) + (unsigned)gx];
    RAW[ly][lx] = v;
  }
  __syncthreads();

  for (int i = tid; i < (OY + 2) * (OX + 2); i += 256) {
    int ey = i / (OX + 2), ex = i - ey * (OX + 2);
    int gy = gy0 + 1 + ey, gx = gx0 + 1 + ex;
    float v = -1e30f;
    if ((unsigned)gy < 1024u && (unsigned)gx < 1024u) {
      v = RAW[ey + 1][ex + 1];
      v = fminf(v, RAW[ey][ex + 1]);
      v = fminf(v, RAW[ey + 2][ex + 1]);
      v = fminf(v, RAW[ey + 1][ex]);
      v = fminf(v, RAW[ey + 1][ex + 2]);
    }
    ER[ey][ex] = v;
  }
  __syncthreads();

  int ox = tid & 63;
  int oyb = tid >> 6;
  float mn = 3.4e38f, mx = -3.4e38f;
#pragma unroll
  for (int k = 0; k < 4; k++) {
    int oy = oyb + 4 * k;
    float v = ER[oy + 1][ox + 1];
    v = fmaxf(v, ER[oy][ox + 1]);
    v = fmaxf(v, ER[oy + 2][ox + 1]);
    v = fmaxf(v, ER[oy + 1][ox]);
    v = fmaxf(v, ER[oy + 1][ox + 2]);
    int gy = gy0 + 2 + oy, gx = gx0 + 2 + ox;
    op[((unsigned)gy << 10) + (unsigned)gx] = v;
    mn = fminf(mn, v);
    mx = fmaxf(mx, v);
  }
#pragma unroll
  for (int o = 16; o; o >>= 1) {
    mn = fminf(mn, __shfl_down_sync(0xffffffffu, mn, o));
    mx = fmaxf(mx, __shfl_down_sync(0xffffffffu, mx, o));
  }
  int w = tid >> 5;
  if ((tid & 31) == 0) { smn[w] = mn; smx[w] = mx; }
  __syncthreads();
  if (tid == 0) {
    for (int i = 1; i < 8; i++) { mn = fminf(mn, smn[i]); mx = fmaxf(mx, smx[i]); }
    unsigned t = s >> 2;
    atomicMin(&g_red[t * 2u],     __float_as_uint(mn));
    atomicMax(&g_red[t * 2u + 1], __float_as_uint(mx));
  }
}

// ---------------------------------------------------------------------------
// persistent propagation. Tile 128x80: 8 warps x (KR=10 rows), 4 cols/lane.
// ---------------------------------------------------------------------------
#define TW 128
#define KR 10
#define TH 80              // 8*KR
#define RSM 8              // halo / max steps per round
#define HX 8
#define IW (TW - 2 * HX)   // 112
#define IH (TH - 2 * RSM)  // 64  (16 * 64 = 1024 exact)
#define NXT 10
#define NYT 16
#define NTILE (NXT * NYT * 8)   // 1280
#define NBLK 444           // 148 SMs x 3 blocks co-resident
#define NR 19              // 18 rounds x 8 steps + 1 round x 6 = 150

__device__ __forceinline__ void gsync() {
  __threadfence();
  __syncthreads();
  if (threadIdx.x == 0) {
    volatile unsigned* vg = &g_bar_gen;
    unsigned gen = *vg;
    if (atomicAdd(&g_bar_cnt, 1u) == NBLK - 1u) {
      atomicExch(&g_bar_cnt, 0u);
      __threadfence();
      *vg = gen + 1u;
    } else {
      while (*vg == gen) { }
      __threadfence();
    }
  }
  __syncthreads();
}

__global__ void __launch_bounds__(256, 3) k_prop_all(float* __restrict__ out) {
  __shared__ int4 Bex[2][2][8][32];   // [parity][top/bot][warp][lane]
  __shared__ unsigned long long sredu[8];
  __shared__ int sredi[8];
  int lane = threadIdx.x & 31;
  int w    = threadIdx.x >> 5;
  int k0   = w * KR;

  int nsg = 0;
  int rnd;
  for (rnd = 0; rnd < NR; rnd++) {
    int steps = (rnd == NR - 1) ? 6 : RSM;
    int* __restrict__ dst = (rnd & 1) ? g_labB : g_labA;
    const int* __restrict__ src = (rnd & 1) ? g_labA : g_labB; // rnd>=1 only
    int roundAny = (rnd == 0) ? 1 : 0;   // thread0-local use

    for (unsigned t = blockIdx.x; t < NTILE; t += NBLK) {
      unsigned s  = t / (NXT * NYT);
      unsigned rr = t - s * (NXT * NYT);
      unsigned ty = rr / NXT;
      unsigned tx = rr - ty * NXT;

      if (rnd > 0) {  // active iff any cone-neighbor changed last round
        int act = 0;
        const int (*pf)[NXT] = g_tflag[(rnd - 1) & 1][s];
        int ylo = (ty > 0) ? (int)ty - 1 : 0, yhi = (ty < NYT - 1) ? (int)ty + 1 : NYT - 1;
        int xlo = (tx > 0) ? (int)tx - 1 : 0, xhi = (tx < NXT - 1) ? (int)tx + 1 : NXT - 1;
        for (int yy = ylo; yy <= yhi; yy++)
          for (int xx = xlo; xx <= xhi; xx++)
            act |= __ldcg(&pf[yy][xx]);
        if (!act) {   // fixed tile: identical in both buffers, zero work
          if (threadIdx.x == 0) __stcg(&g_tflag[rnd & 1][s][ty][tx], 0);
          continue;
        }
      }

      unsigned base = s << 20;
      int gx0 = (int)tx * IW - HX;
      int gy0 = (int)ty * IH - RSM;
      int gx  = gx0 + 4 * lane;           // multiple of 4 -> int4 aligned
      bool xin = (gx >= 0) && (gx <= 1020);
      bool xst = xin && (lane >= 2) && (lane <= 29);

      int c0[KR], c1[KR], c2[KR], c3[KR];

      if (rnd == 0) {
        // fused threshold: labels from opened floats (still live in g_labB)
        unsigned tt = s >> 2;
        float mnv = __uint_as_float(g_red[tt * 2u]);
        float mxv = __uint_as_float(g_red[tt * 2u + 1]);
        float dv  = __fadd_rn(__fsub_rn(mxv, mnv), 1e-10f);
        const float* __restrict__ opf = ((const float*)g_labB) + base;
        unsigned lbase = (s & 3u) << 20;
#pragma unroll
        for (int j = 0; j < KR; j++) {
          int gy = gy0 + k0 + j;
          int l0 = 0, l1 = 0, l2 = 0, l3 = 0;
          if (xin && (unsigned)gy < 1024u) {
            float4 f = *(const float4*)(opf + (((unsigned)gy) << 10) + (unsigned)gx);
            unsigned li = lbase + (((unsigned)gy) << 10) + (unsigned)gx;
            if (__fdiv_rn(__fsub_rn(f.x, mnv), dv) >= 0.5f) l0 = (int)(li + 1u);
            if (__fdiv_rn(__fsub_rn(f.y, mnv), dv) >= 0.5f) l1 = (int)(li + 2u);
            if (__fdiv_rn(__fsub_rn(f.z, mnv), dv) >= 0.5f) l2 = (int)(li + 3u);
            if (__fdiv_rn(__fsub_rn(f.w, mnv), dv) >= 0.5f) l3 = (int)(li + 4u);
          }
          c0[j] = l0; c1[j] = l1; c2[j] = l2; c3[j] = l3;
        }
      } else {
#pragma unroll
        for (int j = 0; j < KR; j++) {
          int gy = gy0 + k0 + j;
          int4 v = make_int4(0, 0, 0, 0);
          if (xin && (unsigned)gy < 1024u)
            v = __ldcg((const int4*)(src + base + (((unsigned)gy) << 10) + (unsigned)gx));
          c0[j] = v.x; c1[j] = v.y; c2[j] = v.z; c3[j] = v.w;
        }
      }

      unsigned f0 = 0u, f1 = 0u, f2 = 0u, f3 = 0u, validm = 0u;
#pragma unroll
      for (int j = 0; j < KR; j++) {
        f0 |= (c0[j] != 0 ? 1u : 0u) << j;
        f1 |= (c1[j] != 0 ? 1u : 0u) << j;
        f2 |= (c2[j] != 0 ? 1u : 0u) << j;
        f3 |= (c3[j] != 0 ? 1u : 0u) << j;
        int row = k0 + j;
        int gy = gy0 + row;
        if (xst && row >= RSM && row < TH - RSM && (unsigned)gy < 1024u)
          validm |= 1u << j;
      }

      if (rnd == 0 && s >= 4u) {          // numSg on interior px of lab
#pragma unroll
        for (int j = 0; j < KR; j++)
          if ((validm >> j) & 1u)
            nsg += ((f0 >> j) & 1) + ((f1 >> j) & 1) + ((f2 >> j) & 1) + ((f3 >> j) & 1);
      }

      for (int it = 0; it < steps; it++) {
        int pp = it & 1;
        Bex[pp][0][w][lane] = make_int4(c0[0], c1[0], c2[0], c3[0]);
        Bex[pp][1][w][lane] = make_int4(c0[KR - 1], c1[KR - 1], c2[KR - 1], c3[KR - 1]);
        __syncthreads();
        int4 ab = (w > 0) ? Bex[pp][1][w - 1][lane] : make_int4(0, 0, 0, 0);
        int4 bl = (w < 7) ? Bex[pp][0][w + 1][lane] : make_int4(0, 0, 0, 0);

        int a0 = ab.x, a1 = ab.y, a2 = ab.z, a3 = ab.w;
        int b0 = c0[0], b1 = c1[0], b2 = c2[0], b3 = c3[0];
#pragma unroll
        for (int j = 0; j < KR; j++) {
          int t0 = (j < KR - 1) ? c0[j + 1] : bl.x;
          int t1 = (j < KR - 1) ? c1[j + 1] : bl.y;
          int t2 = (j < KR - 1) ? c2[j + 1] : bl.z;
          int t3 = (j < KR - 1) ? c3[j + 1] : bl.w;
          int v0 = max3i(a0, b0, t0);
          int v1 = max3i(a1, b1, t1);
          int v2 = max3i(a2, b2, t2);
          int v3 = max3i(a3, b3, t3);
          // lane-edge shfl garbage stays in the discarded halo
          int lft = __shfl_up_sync(0xffffffffu, v3, 1);
          int rgt = __shfl_down_sync(0xffffffffu, v0, 1);
          c0[j] = ((f0 >> j) & 1u) ? max3i(lft, v0, v1) : 0;
          c1[j] = ((f1 >> j) & 1u) ? max3i(v0, v1, v2) : 0;
          c2[j] = ((f2 >> j) & 1u) ? max3i(v1, v2, v3) : 0;
          c3[j] = ((f3 >> j) & 1u) ? max3i(v2, v3, rgt) : 0;
          a0 = b0; a1 = b1; a2 = b2; a3 = b3;
          b0 = t0; b1 = t1; b2 = t2; b3 = t3;
        }
      }

      // store interior + accumulate 64-bit label sum (change detector)
      unsigned long long psum = 0ull;
#pragma unroll
      for (int j = 0; j < KR; j++) {
        if (!((validm >> j) & 1u)) continue;
        int gy = gy0 + k0 + j;
        unsigned off = base + (((unsigned)gy) << 10) + (unsigned)gx;
        __stcg((int4*)(dst + off), make_int4(c0[j], c1[j], c2[j], c3[j]));
        psum += (unsigned long long)(unsigned)(c0[j] + c1[j] + c2[j] + c3[j]);
      }
#pragma unroll
      for (int o = 16; o; o >>= 1)
        psum += __shfl_down_sync(0xffffffffu, psum, o);
      if (lane == 0) sredu[w] = psum;
      __syncthreads();
      if (threadIdx.x == 0) {
        unsigned long long tot = 0ull;
        for (int i = 0; i < 8; i++) tot += sredu[i];
        int tchg;
        if (rnd == 0) tchg = 1;
        else tchg = (tot != __ldcg(&g_tsum[s][ty][tx])) ? 1 : 0;  // monotone sum
        __stcg(&g_tsum[s][ty][tx], tot);
        __stcg(&g_tflag[rnd & 1][s][ty][tx], tchg);
        roundAny |= tchg;
      }
      __syncthreads();
    }

    if (rnd == 0) {                       // block-reduce numSg once
#pragma unroll
      for (int o = 16; o; o >>= 1) nsg += __shfl_down_sync(0xffffffffu, nsg, o);
      if (lane == 0) sredi[w] = nsg;
      __syncthreads();
      if (threadIdx.x == 0) {
        int acc = 0;
        for (int i = 0; i < 8; i++) acc += sredi[i];
        if (acc) atomicAdd(&g_cnt[2], (unsigned)acc);
      }
    }

    if (threadIdx.x == 0 && roundAny) atomicOr(&g_chgs[rnd], 1u);
    gsync();
    if (*(volatile unsigned*)&g_chgs[rnd] == 0u) break;  // global fixed point
  }

  int lastr = (rnd < NR) ? rnd : NR - 1;

  // ---- fused distinct count: v present iff px (v-1) holds label v ----
  const int* __restrict__ fin = (lastr & 1) ? g_labB : g_labA;
  int cnt0 = 0, cnt1 = 0, zer0 = 0, zer1 = 0;
  for (unsigned q = blockIdx.x * 256u + threadIdx.x; q < NPIX / 4u; q += NBLK * 256u) {
    unsigned idx = q * 4u;
    int4 v = __ldcg((const int4*)(fin + idx));
    int wt = (int)(idx & 0x3FFFFFu);
    int m = (v.x == wt + 1) + (v.y == wt + 2) + (v.z == wt + 3) + (v.w == wt + 4);
    int z = (v.x == 0) | (v.y == 0) | (v.z == 0) | (v.w == 0);
    if (idx >> 22) { cnt1 += m; zer1 |= z; } else { cnt0 += m; zer0 |= z; }
  }
#pragma unroll
  for (int o = 16; o; o >>= 1) {
    cnt0 += __shfl_down_sync(0xffffffffu, cnt0, o);
    cnt1 += __shfl_down_sync(0xffffffffu, cnt1, o);
    zer0 |= __shfl_down_sync(0xffffffffu, zer0, o);
    zer1 |= __shfl_down_sync(0xffffffffu, zer1, o);
  }
  __syncthreads();
  if (lane == 0) { sredi[w] = cnt0; }
  __syncthreads();
  if (threadIdx.x == 0) {
    int a = 0; for (int i = 0; i < 8; i++) a += sredi[i];
    if (a) atomicAdd(&g_cnt[0], (unsigned)a);
  }
  __syncthreads();
  if (lane == 0) { sredi[w] = cnt1; }
  __syncthreads();
  if (threadIdx.x == 0) {
    int a = 0; for (int i = 0; i < 8; i++) a += sredi[i];
    if (a) atomicAdd(&g_cnt[1], (unsigned)a);
  }
  if (lane == 0) {
    if (zer0) atomicOr(&g_zf[0], 1u);
    if (zer1) atomicOr(&g_zf[1], 1u);
  }

  gsync();  // all counts visible

  // ---- fused final scalar ----
  if (blockIdx.x == 0 && threadIdx.x == 0) {
    int c0 = (int)__ldcg(&g_cnt[0]) + ((__ldcg(&g_zf[0]) && __ldcg(&fin[0]) != 1) ? 1 : 0);
    int c1 = (int)__ldcg(&g_cnt[1]) + ((__ldcg(&g_zf[1]) && __ldcg(&fin[4u << 20]) != 1) ? 1 : 0);
    float ccs  = (float)c0;
    float ccsg = (float)c1;
    float ns   = (float)__ldcg(&g_cnt[2]);
    out[0] = __fdiv_rn(fabsf(__fsub_rn(ccsg, ccs)), ns);
  }
}

// ---------------------------------------------------------------------------
extern "C" void kernel_launch(void* const* d_in, const int* in_sizes, int n_in,
                              void* d_out, int out_size) {
  const float* img = (const float*)d_in[0];
  const float* lab = (const float*)d_in[1];
  float* out = (float*)d_out;

  k_init<<<1, 32>>>();
  k_open<<<dim3(1024 / OX, 1024 / OY, 8), 256>>>(img, lab);
  k_prop_all<<<NBLK, 256>>>(out);
}